// round 15
// baseline (speedup 1.0000x reference)
#include <cuda_runtime.h>

#define BB   4
#define NIN  128
#define NOUT 128
#define NN   256

// Fused v3 (resubmit after infra failure — design identical to R14 source).
// One block per (b, iblk of 64 rows, o-group of 4): 512 blocks x 256 threads.
//
// Phase 1: thread (ql = t>>6, j4 = t&63) computes the float4 of
//   Pi[b, og*4+ql, 4*j4..+3] and Pj[...] via a 128-deep GEMV into smem.
//
// Phase 2: thread (ql, j4) owns 16 rows. Each 4-row adj group is loaded once
// into registers and reused across the 4 o's. P is re-read from smem inside
// the ol loop (pipelined LDS) instead of living in 16 registers — that is
// what fits the kernel in <=51 regs so 5 blocks/SM (40 warps) stay resident.
//   out[b,o,i,j] = adj[b,i,j] * (i==j ? Pi[o,j] : Pj[o,j])
// Output stores are evict-first (__stcs): the 134MB stream must not evict
// the hot adj/node lines from L2.
__global__ void __launch_bounds__(256, 5)
fused_kernel(const float* __restrict__ node,
             const float* __restrict__ Wi,
             const float* __restrict__ Wj,
             const float4* __restrict__ adj,
             float4* __restrict__ out) {
    __shared__ __align__(16) float s_pi[4 * NN];
    __shared__ __align__(16) float s_pj[4 * NN];

    const int t  = threadIdx.x;                 // 0..255
    const int j4 = t & 63;                      // float4 column index
    const int ql = t >> 6;                      // 0..3

    const int og   = blockIdx.x & 31;           // o-group (fastest varying)
    const int iblk = (blockIdx.x >> 5) & 3;     // 64-row i-block
    const int b    = blockIdx.x >> 7;           // batch

    // -------- Phase 1: projections for o = og*4 + ql --------
    {
        const float4* node4 = (const float4*)(node + b * NIN * NN);  // [c][j4]
        const int o = (og << 2) + ql;
        const float* wi = Wi + o * NIN;
        const float* wj = Wj + o * NIN;

        float aix = 0.f, aiy = 0.f, aiz = 0.f, aiw = 0.f;
        float ajx = 0.f, ajy = 0.f, ajz = 0.f, ajw = 0.f;
#pragma unroll 8
        for (int c = 0; c < NIN; ++c) {
            const float4 nv = __ldg(&node4[(c << 6) + j4]);
            const float wiv = __ldg(&wi[c]);
            const float wjv = __ldg(&wj[c]);
            aix = fmaf(wiv, nv.x, aix); aiy = fmaf(wiv, nv.y, aiy);
            aiz = fmaf(wiv, nv.z, aiz); aiw = fmaf(wiv, nv.w, aiw);
            ajx = fmaf(wjv, nv.x, ajx); ajy = fmaf(wjv, nv.y, ajy);
            ajz = fmaf(wjv, nv.z, ajz); ajw = fmaf(wjv, nv.w, ajw);
        }
        reinterpret_cast<float4*>(s_pi)[(ql << 6) + j4] =
            make_float4(aix, aiy, aiz, aiw);
        reinterpret_cast<float4*>(s_pj)[(ql << 6) + j4] =
            make_float4(ajx, ajy, ajz, ajw);
    }
    __syncthreads();

    // -------- Phase 2: stream 64 rows x 4 o-images --------
    const float4* adj_b    = adj + ((unsigned)b << 14);
    float4*       out_base = out + (((unsigned)(b << 7) + (og << 2)) << 14);
    const float4* pj4      = reinterpret_cast<const float4*>(s_pj);
    const int     row_base = (iblk << 6) + (ql << 4);

    for (int g = 0; g < 4; ++g) {
        const int i0 = row_base + (g << 2);      // 4-aligned row group

        const float4 a0 = __ldg(&adj_b[((i0 + 0) << 6) + j4]);
        const float4 a1 = __ldg(&adj_b[((i0 + 1) << 6) + j4]);
        const float4 a2 = __ldg(&adj_b[((i0 + 2) << 6) + j4]);
        const float4 a3 = __ldg(&adj_b[((i0 + 3) << 6) + j4]);

        const bool diag = ((i0 >> 2) == j4);

#pragma unroll
        for (int ol = 0; ol < 4; ++ol) {
            // P re-read from smem each iteration: keeps register count low.
            const float4 p = pj4[(ol << 6) + j4];

            float4 r0, r1, r2, r3;
            r0.x = a0.x * p.x; r0.y = a0.y * p.y; r0.z = a0.z * p.z; r0.w = a0.w * p.w;
            r1.x = a1.x * p.x; r1.y = a1.y * p.y; r1.z = a1.z * p.z; r1.w = a1.w * p.w;
            r2.x = a2.x * p.x; r2.y = a2.y * p.y; r2.z = a2.z * p.z; r2.w = a2.w * p.w;
            r3.x = a3.x * p.x; r3.y = a3.y * p.y; r3.z = a3.z * p.z; r3.w = a3.w * p.w;

            if (diag) {   // rows i0..i0+3 hold diagonal elements at lanes 0..3
                r0.x = a0.x * s_pi[(ol << 8) + i0 + 0];
                r1.y = a1.y * s_pi[(ol << 8) + i0 + 1];
                r2.z = a2.z * s_pi[(ol << 8) + i0 + 2];
                r3.w = a3.w * s_pi[(ol << 8) + i0 + 3];
            }

            float4* dst = out_base + ((unsigned)ol << 14);
            __stcs(&dst[((i0 + 0) << 6) + j4], r0);
            __stcs(&dst[((i0 + 1) << 6) + j4], r1);
            __stcs(&dst[((i0 + 2) << 6) + j4], r2);
            __stcs(&dst[((i0 + 3) << 6) + j4], r3);
        }
    }
}

extern "C" void kernel_launch(void* const* d_in, const int* in_sizes, int n_in,
                              void* d_out, int out_size) {
    const float* adj  = (const float*)d_in[0];  // [B,1,N,N]
    const float* node = (const float*)d_in[1];  // [B,NIN,N]
    const float* Wi   = (const float*)d_in[2];  // [NOUT,NIN]
    const float* Wj   = (const float*)d_in[3];  // [NOUT,NIN]
    float* out = (float*)d_out;                 // [B,NOUT,N,N]

    (void)in_sizes; (void)n_in; (void)out_size;

    fused_kernel<<<BB * 4 * 32, 256>>>(node, Wi, Wj,
                                       (const float4*)adj, (float4*)out);
}

// round 16
// speedup vs baseline: 1.4423x; 1.4423x over previous
#include <cuda_runtime.h>

#define BB   4
#define NIN  128
#define NOUT 128
#define NN   256

// Fused v4. Grid = 4b x 64 o-pairs x 4 i-blocks = 1024 blocks x 256 threads.
// Lessons encoded: P in REGISTERS (2 float4 only), grid >= 1024 so occupancy
// isn't grid-capped, <=51 regs via __launch_bounds__(256,5), proj head halved
// by split-c so the head stays small relative to phase 2.
//
// Phase 1 (split-c proj): thread (h = t>>6, j4 = t&63), o_l = h&1, ch = h>>1:
//   partial Pi/Pj float4 for o = og*2+o_l over c in [ch*64, ch*64+64).
//   Partials land in smem; a 1-step reduce produces final Pi/Pj.
// Phase 2 (expand): thread (ql = t>>6, j4) owns 16 rows of this block's
//   64-row slice. Each 4-row adj group is loaded once and reused for BOTH o's:
//     out[b,o,i,j] = adj[b,i,j] * (i==j ? Pi[o,j] : Pj[o,j])
//   P is in registers; s_pi is touched only in the rare diagonal branch.
// Output stores evict-first (__stcs): 134MB stream must not evict hot lines.
__global__ void __launch_bounds__(256, 5)
fused_kernel(const float* __restrict__ node,
             const float* __restrict__ Wi,
             const float* __restrict__ Wj,
             const float4* __restrict__ adj,
             float4* __restrict__ out) {
    __shared__ __align__(16) float4 part_i[2][2][64];   // [o_l][ch][j4] 2KB
    __shared__ __align__(16) float4 part_j[2][2][64];   // 2KB
    __shared__ __align__(16) float  s_pi[2 * NN];       // final Pi, 2KB
    __shared__ __align__(16) float  s_pj[2 * NN];       // final Pj, 2KB

    const int t  = threadIdx.x;               // 0..255
    const int j4 = t & 63;
    const int h  = t >> 6;                    // 0..3

    const int og   = blockIdx.x & 63;         // o-pair (fastest: L2 adj share)
    const int iblk = (blockIdx.x >> 6) & 3;   // 64-row i-block
    const int b    = blockIdx.x >> 8;         // batch

    // ---- Phase 1: split-c partial GEMV (64 iterations) ----
    {
        const int o_l = h & 1;
        const int ch  = h >> 1;                       // c-half
        const int o   = (og << 1) + o_l;
        const float4* node4 = (const float4*)(node + b * NIN * NN)
                              + (ch << 12);           // + ch*64*64 float4
        const float* wi = Wi + o * NIN + (ch << 6);
        const float* wj = Wj + o * NIN + (ch << 6);

        float aix = 0.f, aiy = 0.f, aiz = 0.f, aiw = 0.f;
        float ajx = 0.f, ajy = 0.f, ajz = 0.f, ajw = 0.f;
#pragma unroll 8
        for (int c = 0; c < 64; ++c) {
            const float4 nv = __ldg(&node4[(c << 6) + j4]);
            const float wiv = __ldg(&wi[c]);
            const float wjv = __ldg(&wj[c]);
            aix = fmaf(wiv, nv.x, aix); aiy = fmaf(wiv, nv.y, aiy);
            aiz = fmaf(wiv, nv.z, aiz); aiw = fmaf(wiv, nv.w, aiw);
            ajx = fmaf(wjv, nv.x, ajx); ajy = fmaf(wjv, nv.y, ajy);
            ajz = fmaf(wjv, nv.z, ajz); ajw = fmaf(wjv, nv.w, ajw);
        }
        part_i[o_l][ch][j4] = make_float4(aix, aiy, aiz, aiw);
        part_j[o_l][ch][j4] = make_float4(ajx, ajy, ajz, ajw);
    }
    __syncthreads();

    // ---- Reduce the two c-halves: t<128 does Pi, t>=128 does Pj ----
    {
        const int o_l = (t >> 6) & 1;
        const int jj  = t & 63;
        if (t < 128) {
            const float4 u = part_i[o_l][0][jj];
            const float4 v = part_i[o_l][1][jj];
            reinterpret_cast<float4*>(s_pi)[(o_l << 6) + jj] =
                make_float4(u.x + v.x, u.y + v.y, u.z + v.z, u.w + v.w);
        } else {
            const float4 u = part_j[o_l][0][jj];
            const float4 v = part_j[o_l][1][jj];
            reinterpret_cast<float4*>(s_pj)[(o_l << 6) + jj] =
                make_float4(u.x + v.x, u.y + v.y, u.z + v.z, u.w + v.w);
        }
    }
    __syncthreads();

    // ---- Phase 2: stream 64 rows x 2 o-images, adj reused across o ----
    const float4 P0 = reinterpret_cast<const float4*>(s_pj)[j4];        // o_l=0
    const float4 P1 = reinterpret_cast<const float4*>(s_pj)[64 + j4];   // o_l=1

    const float4* adj_b = adj + ((unsigned)b << 14);
    float4* out0 = out + (((unsigned)(b << 7) + (og << 1)) << 14);
    float4* out1 = out0 + (1u << 14);

    const int row_base = (iblk << 6) + (h << 4);     // 16 rows for this thread

#pragma unroll
    for (int g = 0; g < 4; ++g) {
        const int i0 = row_base + (g << 2);          // 4-aligned row group

        const float4 a0 = __ldg(&adj_b[((i0 + 0) << 6) + j4]);
        const float4 a1 = __ldg(&adj_b[((i0 + 1) << 6) + j4]);
        const float4 a2 = __ldg(&adj_b[((i0 + 2) << 6) + j4]);
        const float4 a3 = __ldg(&adj_b[((i0 + 3) << 6) + j4]);

        const bool diag = ((i0 >> 2) == j4);

        // o_l = 0
        {
            float4 r0, r1, r2, r3;
            r0.x = a0.x * P0.x; r0.y = a0.y * P0.y; r0.z = a0.z * P0.z; r0.w = a0.w * P0.w;
            r1.x = a1.x * P0.x; r1.y = a1.y * P0.y; r1.z = a1.z * P0.z; r1.w = a1.w * P0.w;
            r2.x = a2.x * P0.x; r2.y = a2.y * P0.y; r2.z = a2.z * P0.z; r2.w = a2.w * P0.w;
            r3.x = a3.x * P0.x; r3.y = a3.y * P0.y; r3.z = a3.z * P0.z; r3.w = a3.w * P0.w;
            if (diag) {
                r0.x = a0.x * s_pi[i0 + 0];
                r1.y = a1.y * s_pi[i0 + 1];
                r2.z = a2.z * s_pi[i0 + 2];
                r3.w = a3.w * s_pi[i0 + 3];
            }
            __stcs(&out0[((i0 + 0) << 6) + j4], r0);
            __stcs(&out0[((i0 + 1) << 6) + j4], r1);
            __stcs(&out0[((i0 + 2) << 6) + j4], r2);
            __stcs(&out0[((i0 + 3) << 6) + j4], r3);
        }
        // o_l = 1
        {
            float4 r0, r1, r2, r3;
            r0.x = a0.x * P1.x; r0.y = a0.y * P1.y; r0.z = a0.z * P1.z; r0.w = a0.w * P1.w;
            r1.x = a1.x * P1.x; r1.y = a1.y * P1.y; r1.z = a1.z * P1.z; r1.w = a1.w * P1.w;
            r2.x = a2.x * P1.x; r2.y = a2.y * P1.y; r2.z = a2.z * P1.z; r2.w = a2.w * P1.w;
            r3.x = a3.x * P1.x; r3.y = a3.y * P1.y; r3.z = a3.z * P1.z; r3.w = a3.w * P1.w;
            if (diag) {
                r0.x = a0.x * s_pi[NN + i0 + 0];
                r1.y = a1.y * s_pi[NN + i0 + 1];
                r2.z = a2.z * s_pi[NN + i0 + 2];
                r3.w = a3.w * s_pi[NN + i0 + 3];
            }
            __stcs(&out1[((i0 + 0) << 6) + j4], r0);
            __stcs(&out1[((i0 + 1) << 6) + j4], r1);
            __stcs(&out1[((i0 + 2) << 6) + j4], r2);
            __stcs(&out1[((i0 + 3) << 6) + j4], r3);
        }
    }
}

extern "C" void kernel_launch(void* const* d_in, const int* in_sizes, int n_in,
                              void* d_out, int out_size) {
    const float* adj  = (const float*)d_in[0];  // [B,1,N,N]
    const float* node = (const float*)d_in[1];  // [B,NIN,N]
    const float* Wi   = (const float*)d_in[2];  // [NOUT,NIN]
    const float* Wj   = (const float*)d_in[3];  // [NOUT,NIN]
    float* out = (float*)d_out;                 // [B,NOUT,N,N]

    (void)in_sizes; (void)n_in; (void)out_size;

    fused_kernel<<<BB * 64 * 4, 256>>>(node, Wi, Wj,
                                       (const float4*)adj, (float4*)out);
}

// round 17
// speedup vs baseline: 1.8918x; 1.3116x over previous
#include <cuda_runtime.h>

#define BB   4
#define NIN  128
#define NOUT 128
#define NN   256

// Fused v5: grid = 512 blocks (one per (b,o)) x 512 THREADS.
// Why 512 threads: at 256 thr/block a 512-block grid caps occupancy at ~43%
// (R6's ceiling). 16-warp blocks raise the ceiling to 3 blocks/SM = 48 warps
// (75%) at the SAME grid, i.e. without duplicating the proj head (head node
// traffic stays at the 64MB minimum — every >512-block variant regressed on
// exactly that duplication).
//
// Phase 1 (split-c x8): thread (h = t>>6 in 0..7, j4 = t&63) runs a
//   16-iteration GEMV chunk over c in [16h, 16h+16) producing partial float4
//   of Pi/Pj for this block's o. 8x shorter dependent-load chain than R6.
//   Partials reduce through smem (128 threads) into s_pi/s_pj.
// Phase 2: thread (h, j4) streams rows [32h, 32h+32), 8 groups of 4 rows.
//   adj loaded straight from L2 (no smem staging - R10 showed LDS competes
//   with STG in L1TEX), P in ONE register float4 (R15 lesson), diagonal fix
//   touches s_pi only on the rare (i0>>2)==j4 group.
// Output stores evict-first (__stcs): 134MB stream must not evict hot lines.
__global__ void __launch_bounds__(512, 3)
fused_kernel(const float* __restrict__ node,
             const float* __restrict__ Wi,
             const float* __restrict__ Wj,
             const float4* __restrict__ adj,
             float4* __restrict__ out) {
    __shared__ __align__(16) float4 part_i[8][64];   // [h][j4] 8KB
    __shared__ __align__(16) float4 part_j[8][64];   // 8KB
    __shared__ __align__(16) float  s_pi[NN];        // 1KB
    __shared__ __align__(16) float  s_pj[NN];        // 1KB

    const int t  = threadIdx.x;            // 0..511
    const int j4 = t & 63;
    const int h  = t >> 6;                 // 0..7

    const int o  = blockIdx.x & (NOUT - 1);
    const int b  = blockIdx.x >> 7;

    // ---- Phase 1: 16-iteration partial GEMV for c-chunk h ----
    {
        const float4* node4 = (const float4*)(node + b * NIN * NN);
        const float*  wi    = Wi + o * NIN + (h << 4);
        const float*  wj    = Wj + o * NIN + (h << 4);
        const int     cbase = h << 4;

        float aix = 0.f, aiy = 0.f, aiz = 0.f, aiw = 0.f;
        float ajx = 0.f, ajy = 0.f, ajz = 0.f, ajw = 0.f;
#pragma unroll
        for (int cc = 0; cc < 16; ++cc) {
            const float4 nv = __ldg(&node4[((cbase + cc) << 6) + j4]);
            const float wiv = __ldg(&wi[cc]);
            const float wjv = __ldg(&wj[cc]);
            aix = fmaf(wiv, nv.x, aix); aiy = fmaf(wiv, nv.y, aiy);
            aiz = fmaf(wiv, nv.z, aiz); aiw = fmaf(wiv, nv.w, aiw);
            ajx = fmaf(wjv, nv.x, ajx); ajy = fmaf(wjv, nv.y, ajy);
            ajz = fmaf(wjv, nv.z, ajz); ajw = fmaf(wjv, nv.w, ajw);
        }
        part_i[h][j4] = make_float4(aix, aiy, aiz, aiw);
        part_j[h][j4] = make_float4(ajx, ajy, ajz, ajw);
    }
    __syncthreads();

    // ---- Reduce 8 partials: threads 0..63 -> Pi, 64..127 -> Pj ----
    if (t < 128) {
        const int jj = t & 63;
        float4 acc = make_float4(0.f, 0.f, 0.f, 0.f);
        if (t < 64) {
#pragma unroll
            for (int hh = 0; hh < 8; ++hh) {
                const float4 u = part_i[hh][jj];
                acc.x += u.x; acc.y += u.y; acc.z += u.z; acc.w += u.w;
            }
            reinterpret_cast<float4*>(s_pi)[jj] = acc;
        } else {
#pragma unroll
            for (int hh = 0; hh < 8; ++hh) {
                const float4 u = part_j[hh][jj];
                acc.x += u.x; acc.y += u.y; acc.z += u.z; acc.w += u.w;
            }
            reinterpret_cast<float4*>(s_pj)[jj] = acc;
        }
    }
    __syncthreads();

    // ---- Phase 2: stream 32 rows per thread ----
    const float4 P = reinterpret_cast<const float4*>(s_pj)[j4];

    const float4* adj_b  = adj + ((unsigned)b << 14);
    float4*       out_bo = out + (((unsigned)(b << 7) + o) << 14);
    const int     row_base = h << 5;

#pragma unroll 2
    for (int g = 0; g < 8; ++g) {
        const int i0 = row_base + (g << 2);      // 4-aligned row group

        const float4 a0 = __ldg(&adj_b[((i0 + 0) << 6) + j4]);
        const float4 a1 = __ldg(&adj_b[((i0 + 1) << 6) + j4]);
        const float4 a2 = __ldg(&adj_b[((i0 + 2) << 6) + j4]);
        const float4 a3 = __ldg(&adj_b[((i0 + 3) << 6) + j4]);

        float4 r0, r1, r2, r3;
        r0.x = a0.x * P.x; r0.y = a0.y * P.y; r0.z = a0.z * P.z; r0.w = a0.w * P.w;
        r1.x = a1.x * P.x; r1.y = a1.y * P.y; r1.z = a1.z * P.z; r1.w = a1.w * P.w;
        r2.x = a2.x * P.x; r2.y = a2.y * P.y; r2.z = a2.z * P.z; r2.w = a2.w * P.w;
        r3.x = a3.x * P.x; r3.y = a3.y * P.y; r3.z = a3.z * P.z; r3.w = a3.w * P.w;

        if ((i0 >> 2) == j4) {   // rows i0..i0+3 hold diagonal at lanes 0..3
            r0.x = a0.x * s_pi[i0 + 0];
            r1.y = a1.y * s_pi[i0 + 1];
            r2.z = a2.z * s_pi[i0 + 2];
            r3.w = a3.w * s_pi[i0 + 3];
        }

        __stcs(&out_bo[((i0 + 0) << 6) + j4], r0);
        __stcs(&out_bo[((i0 + 1) << 6) + j4], r1);
        __stcs(&out_bo[((i0 + 2) << 6) + j4], r2);
        __stcs(&out_bo[((i0 + 3) << 6) + j4], r3);
    }
}

extern "C" void kernel_launch(void* const* d_in, const int* in_sizes, int n_in,
                              void* d_out, int out_size) {
    const float* adj  = (const float*)d_in[0];  // [B,1,N,N]
    const float* node = (const float*)d_in[1];  // [B,NIN,N]
    const float* Wi   = (const float*)d_in[2];  // [NOUT,NIN]
    const float* Wj   = (const float*)d_in[3];  // [NOUT,NIN]
    float* out = (float*)d_out;                 // [B,NOUT,N,N]

    (void)in_sizes; (void)n_in; (void)out_size;

    fused_kernel<<<BB * NOUT, 512>>>(node, Wi, Wj,
                                     (const float4*)adj, (float4*)out);
}